// round 4
// baseline (speedup 1.0000x reference)
#include <cuda_runtime.h>
#include <math.h>

#define BB 8
#define TT 8192
#define DD 128
#define KD 64
#define NTHREADS 256

// GEMM kernel geometry
#define GROWS 256                 // rows per GEMM block
#define NGEMM (BB * TT / GROWS)   // 256 GEMM blocks (+1 prep block)

// Scan kernel geometry
#define CL2 128                   // timesteps per scan chunk
#define NCHUNK2 (TT / CL2)        // 64
#define NSCAN (BB * NCHUNK2)      // 512 scan blocks
#define NGROUP 4
#define GLEN (CL2 / NGROUP)       // 32

typedef unsigned long long ull;

// ---------------- device globals (no allocation allowed) ----------------
__device__ float g_u[BB * TT * KD];      // 16MB scratch: raw u = x @ W^T (unnormalized)
__device__ float g_a0[KD];
__device__ float g_w0[KD];
__device__ float g_bias[KD];
__device__ float g_invs;

__device__ float g_aggL[NSCAN * KD * 4]; // local  (Zr,Zi,Ur,Ui)
__device__ float g_aggI[NSCAN * KD * 4]; // inclusive
__device__ int   g_flag[NSCAN];

// ---------------- helpers ----------------
__device__ __forceinline__ float softplusf(float x) {
    return (x > 20.0f) ? x : log1pf(expf(x));
}

// z = rho * e^{i theta}; alpha·dt and theta are tiny (<~2e-3) -> Taylor.
__device__ __forceinline__ void zval2(float am, float om_, float tm, float dtv,
                                      float a0k, float w0k, float& rc, float& rs) {
    float ea = __expf(am + tm);
    float eo = __expf(om_ + tm);
    float x  = a0k * ea * dtv;                       // alpha*dt  (<= ~2e-3)
    float th = w0k * eo * dtv;                       // theta     (<= ~2e-3)
    float rho = 1.0f - x * fmaf(-0.5f, x, 1.0f);     // e^-x: 1 - x + x^2/2
    float th2 = th * th;
    float ct  = fmaf(-0.5f, th2, 1.0f);              // cos: 1 - th^2/2
    float st  = th * fmaf(-0.16666667f, th2, 1.0f);  // sin: th - th^3/6
    rc = rho * ct;
    rs = rho * st;
}

__device__ __forceinline__ ull pk2(float v) {
    ull r;
    asm("mov.b64 %0, {%1, %1};" : "=l"(r) : "f"(v));
    return r;
}
__device__ __forceinline__ void fma2(ull& d, ull a, ull b) {
    asm("fma.rn.f32x2 %0, %1, %2, %0;" : "+l"(d) : "l"(a), "l"(b));
}
__device__ __forceinline__ void upk(ull v, float& lo, float& hi) {
    asm("mov.b64 {%0, %1}, %2;" : "=f"(lo), "=f"(hi) : "l"(v));
}

// ---------------- prep (runs in dedicated block of GEMM kernel) ----------------
__device__ void do_prep(float* sm, const float* __restrict__ W,
                        const float* __restrict__ bvec,
                        const float* __restrict__ s_real,
                        const float* __restrict__ s_imag,
                        const float* __restrict__ tau_raw, int tid) {
    float* WsT = sm;                 // 128 x 68
    float* Gm  = WsT + 128 * 68;     // 64 x 68
    float* Am  = Gm + 64 * 68;
    float* Bm  = Am + 64 * 68;
    float* pv  = Bm + 64 * 68;       // 64
    float* py  = pv + 64;
    float* pred = py + 64;

    // reset lookback flags for the scan kernel (512 flags, 256 threads)
    g_flag[tid] = 0;
    g_flag[tid + 256] = 0;

    // load W transposed into smem: WsT[d][k]
    for (int i = tid; i < 64 * 32; i += NTHREADS) {
        int k = i >> 5, q = i & 31;
        float4 w4 = *(const float4*)&W[k * DD + q * 4];
        WsT[(q * 4 + 0) * 68 + k] = w4.x;
        WsT[(q * 4 + 1) * 68 + k] = w4.y;
        WsT[(q * 4 + 2) * 68 + k] = w4.z;
        WsT[(q * 4 + 3) * 68 + k] = w4.w;
    }
    __syncthreads();

    const int i0 = (tid >> 4) * 4;
    const int j0 = (tid & 15) * 4;

    // G = W W^T via FFMA2
    {
        ull acc2[4][2];
#pragma unroll
        for (int a = 0; a < 4; a++) { acc2[a][0] = 0ull; acc2[a][1] = 0ull; }
        for (int d = 0; d < DD; d++) {
            float4 si = *(const float4*)&WsT[d * 68 + i0];
            ull sj0 = *(const ull*)&WsT[d * 68 + j0];
            ull sj1 = *(const ull*)&WsT[d * 68 + j0 + 2];
            ull xx;
            xx = pk2(si.x); fma2(acc2[0][0], xx, sj0); fma2(acc2[0][1], xx, sj1);
            xx = pk2(si.y); fma2(acc2[1][0], xx, sj0); fma2(acc2[1][1], xx, sj1);
            xx = pk2(si.z); fma2(acc2[2][0], xx, sj0); fma2(acc2[2][1], xx, sj1);
            xx = pk2(si.w); fma2(acc2[3][0], xx, sj0); fma2(acc2[3][1], xx, sj1);
        }
#pragma unroll
        for (int a = 0; a < 4; a++) {
            float lo, hi;
            upk(acc2[a][0], lo, hi);
            Gm[(i0 + a) * 68 + j0 + 0] = lo; Gm[(i0 + a) * 68 + j0 + 1] = hi;
            upk(acc2[a][1], lo, hi);
            Gm[(i0 + a) * 68 + j0 + 2] = lo; Gm[(i0 + a) * 68 + j0 + 3] = hi;
        }
    }
    __syncthreads();

    // 4 squarings: M = G^16
    const float* srcs[4] = {Gm, Am, Bm, Am};
    float* dsts[4] = {Am, Bm, Am, Bm};
    for (int sq = 0; sq < 4; sq++) {
        const float* src = srcs[sq];
        float* dst = dsts[sq];
        ull acc2[4][2];
#pragma unroll
        for (int a = 0; a < 4; a++) { acc2[a][0] = 0ull; acc2[a][1] = 0ull; }
        for (int l = 0; l < 64; l++) {
            float4 si = *(const float4*)&src[l * 68 + i0];
            ull sj0 = *(const ull*)&src[l * 68 + j0];
            ull sj1 = *(const ull*)&src[l * 68 + j0 + 2];
            ull xx;
            xx = pk2(si.x); fma2(acc2[0][0], xx, sj0); fma2(acc2[0][1], xx, sj1);
            xx = pk2(si.y); fma2(acc2[1][0], xx, sj0); fma2(acc2[1][1], xx, sj1);
            xx = pk2(si.z); fma2(acc2[2][0], xx, sj0); fma2(acc2[2][1], xx, sj1);
            xx = pk2(si.w); fma2(acc2[3][0], xx, sj0); fma2(acc2[3][1], xx, sj1);
        }
        __syncthreads();
#pragma unroll
        for (int a = 0; a < 4; a++) {
            float lo, hi;
            upk(acc2[a][0], lo, hi);
            dst[(i0 + a) * 68 + j0 + 0] = lo; dst[(i0 + a) * 68 + j0 + 1] = hi;
            upk(acc2[a][1], lo, hi);
            dst[(i0 + a) * 68 + j0 + 2] = lo; dst[(i0 + a) * 68 + j0 + 3] = hi;
        }
        __syncthreads();
    }

    if (tid < 64) pv[tid] = 1.0f + 0.001f * (float)tid;
    __syncthreads();

    for (int it = 0; it < 8; it++) {
        if (tid < 64) {
            float s = 0.0f;
#pragma unroll 4
            for (int j = 0; j < 64; j += 4) {
                float4 m4 = *(const float4*)&Bm[tid * 68 + j];
                float4 v4 = *(const float4*)&pv[j];
                s = fmaf(m4.x, v4.x, s);
                s = fmaf(m4.y, v4.y, s);
                s = fmaf(m4.z, v4.z, s);
                s = fmaf(m4.w, v4.w, s);
            }
            py[tid] = s;
            pred[tid] = s * s;
        }
        __syncthreads();
        for (int s = 32; s > 0; s >>= 1) {
            if (tid < s) pred[tid] += pred[tid + s];
            __syncthreads();
        }
        if (tid < 64) pv[tid] = py[tid] * rsqrtf(pred[0]);
        __syncthreads();
    }

    // Rayleigh on original G
    if (tid < 64) {
        float s = 0.0f;
#pragma unroll 4
        for (int j = 0; j < 64; j += 4) {
            float4 m4 = *(const float4*)&Gm[tid * 68 + j];
            float4 v4 = *(const float4*)&pv[j];
            s = fmaf(m4.x, v4.x, s);
            s = fmaf(m4.y, v4.y, s);
            s = fmaf(m4.z, v4.z, s);
            s = fmaf(m4.w, v4.w, s);
        }
        pred[tid] = pv[tid] * s;
    }
    __syncthreads();
    for (int s = 32; s > 0; s >>= 1) {
        if (tid < s) pred[tid] += pred[tid + s];
        __syncthreads();
    }
    if (tid == 0) g_invs = 1.0f / sqrtf(pred[0]);
    if (tid < 64) {
        float tau = softplusf(tau_raw[0]) + 1e-3f;
        g_a0[tid] = (softplusf(s_real[tid]) + 1e-6f) * tau;
        g_w0[tid] = s_imag[tid] * tau;
        g_bias[tid] = bvec[tid];
    }
}

// ---------------- kernel A: GEMM (u = x @ W^T, unnormalized) + prep block ----------------
__global__ void __launch_bounds__(NTHREADS, 2)
gemm_kernel(const float* __restrict__ x, const float* __restrict__ W,
            const float* __restrict__ bvec, const float* __restrict__ s_real,
            const float* __restrict__ s_imag, const float* __restrict__ tau_raw) {
    extern __shared__ float sm[];
    const int bid = blockIdx.x;
    const int tid = threadIdx.x;

    if (bid >= NGEMM) {           // dedicated prep block
        do_prep(sm, W, bvec, s_real, s_imag, tau_raw, tid);
        return;
    }

    float* xs = sm;               // 256 x 36
    float* wc = xs + 256 * 36;    // 32 x 64

    const int ty = tid >> 3;      // 0..31 : 8 t rows each
    const int tx = tid & 7;       // 0..7  : 8 k cols each

    ull acc[8][4];
#pragma unroll
    for (int i = 0; i < 8; i++)
#pragma unroll
        for (int p = 0; p < 4; p++) acc[i][p] = 0ull;

    const float* xg_base = x + (size_t)bid * GROWS * DD;
    const int kk = tid & 63;
    const int qq = tid >> 6;      // 0..3

    for (int dc = 0; dc < 4; dc++) {   // d chunks of 32
        __syncthreads();
        // stage x chunk: 256 rows x 32 d
#pragma unroll
        for (int j = 0; j < 8; j++) {
            int f = tid + j * NTHREADS;
            int row = f >> 3, q = f & 7;
            *(float4*)&xs[row * 36 + q * 4] =
                *(const float4*)&xg_base[(size_t)row * DD + dc * 32 + q * 4];
        }
        // stage W chunk transposed: wc[d][k]
        {
            float4 w4a = *(const float4*)&W[kk * DD + dc * 32 + qq * 8];
            float4 w4b = *(const float4*)&W[kk * DD + dc * 32 + qq * 8 + 4];
            wc[(qq * 8 + 0) * 64 + kk] = w4a.x;
            wc[(qq * 8 + 1) * 64 + kk] = w4a.y;
            wc[(qq * 8 + 2) * 64 + kk] = w4a.z;
            wc[(qq * 8 + 3) * 64 + kk] = w4a.w;
            wc[(qq * 8 + 4) * 64 + kk] = w4b.x;
            wc[(qq * 8 + 5) * 64 + kk] = w4b.y;
            wc[(qq * 8 + 6) * 64 + kk] = w4b.z;
            wc[(qq * 8 + 7) * 64 + kk] = w4b.w;
        }
        __syncthreads();

#pragma unroll 1
        for (int d4 = 0; d4 < 8; d4++) {          // quads of 4 d
            float4 xv[8];
#pragma unroll
            for (int i = 0; i < 8; i++)
                xv[i] = *(const float4*)&xs[(ty * 8 + i) * 36 + d4 * 4];
            ull wv[4][4];
#pragma unroll
            for (int dd = 0; dd < 4; dd++) {
                const ull* wp = (const ull*)&wc[(d4 * 4 + dd) * 64 + tx * 8];
#pragma unroll
                for (int p = 0; p < 4; p++) wv[dd][p] = wp[p];
            }
#pragma unroll
            for (int i = 0; i < 8; i++) {
                ull xx;
                xx = pk2(xv[i].x);
#pragma unroll
                for (int p = 0; p < 4; p++) fma2(acc[i][p], xx, wv[0][p]);
                xx = pk2(xv[i].y);
#pragma unroll
                for (int p = 0; p < 4; p++) fma2(acc[i][p], xx, wv[1][p]);
                xx = pk2(xv[i].z);
#pragma unroll
                for (int p = 0; p < 4; p++) fma2(acc[i][p], xx, wv[2][p]);
                xx = pk2(xv[i].w);
#pragma unroll
                for (int p = 0; p < 4; p++) fma2(acc[i][p], xx, wv[3][p]);
            }
        }
    }

    // write raw u to gmem scratch
#pragma unroll
    for (int i = 0; i < 8; i++) {
        ull* up = (ull*)&g_u[((size_t)bid * GROWS + ty * 8 + i) * KD + tx * 8];
#pragma unroll
        for (int p = 0; p < 4; p++) up[p] = acc[i][p];
    }
}

// ---------------- kernel B: scan (compose + lookback + replay) ----------------
__global__ void __launch_bounds__(NTHREADS)
scan_kernel(const float* __restrict__ dtv_g, const float* __restrict__ amod,
            const float* __restrict__ omod, const float* __restrict__ tmod,
            float* __restrict__ out) {
    __shared__ float agg[NGROUP * KD * 4];
    __shared__ float pre[NGROUP * KD * 4];
    __shared__ float carry[2 * KD];

    const int bid   = blockIdx.x;
    const int b     = bid % BB;
    const int chunk = bid / BB;
    const int tid   = threadIdx.x;
    const int t0    = chunk * CL2;
    const int fidx  = b * NCHUNK2 + chunk;

    const int k = tid & 63;
    const int g = tid >> 6;
    const float a0k = g_a0[k];
    const float w0k = g_w0[k];
    const float invs = g_invs;
    const float bk = g_bias[k];

    const size_t base_bt = (size_t)b * TT + t0 + g * GLEN;
    const float* amp = amod + base_bt * KD + k;
    const float* omp_ = omod + base_bt * KD + k;
    const float* tmp_ = tmod + base_bt;
    const float* dtp = dtv_g + base_bt;
    const float* up_ = g_u + base_bt * KD + k;

    // ---------- compose (carry-free) ----------
    float Zr = 1.0f, Zi = 0.0f, Ur = 0.0f, Ui = 0.0f;
#pragma unroll 4
    for (int i = 0; i < GLEN; i++) {
        float rc, rs;
        zval2(amp[(size_t)i * KD], omp_[(size_t)i * KD], tmp_[i], dtp[i], a0k, w0k, rc, rs);
        float u = fmaf(up_[(size_t)i * KD], invs, bk);
        float Ur2 = fmaf(rc, Ur, fmaf(-rs, Ui, u));
        float Ui2 = fmaf(rc, Ui, rs * Ur);
        float Zr2 = fmaf(rc, Zr, -rs * Zi);
        float Zi2 = fmaf(rc, Zi, rs * Zr);
        Ur = Ur2; Ui = Ui2; Zr = Zr2; Zi = Zi2;
    }
    {
        float* a = &agg[(g * 64 + k) * 4];
        a[0] = Zr; a[1] = Zi; a[2] = Ur; a[3] = Ui;
    }
    __syncthreads();

    // ---------- intra-block group scan + publish local aggregate ----------
    float bzr = 1.0f, bzi = 0.0f, bur = 0.0f, bui = 0.0f;
    if (tid < 64) {
        float zr = 1.0f, zi = 0.0f, ur = 0.0f, ui = 0.0f;
#pragma unroll
        for (int gg = 0; gg < NGROUP; gg++) {
            float* p = &pre[(gg * 64 + k) * 4];
            p[0] = zr; p[1] = zi; p[2] = ur; p[3] = ui;
            float* a = &agg[(gg * 64 + k) * 4];
            float azr = a[0], azi = a[1], aur = a[2], aui = a[3];
            float nzr = azr * zr - azi * zi;
            float nzi = azr * zi + azi * zr;
            float nur = fmaf(azr, ur, fmaf(-azi, ui, aur));
            float nui = fmaf(azr, ui, fmaf(azi, ur, aui));
            zr = nzr; zi = nzi; ur = nur; ui = nui;
        }
        bzr = zr; bzi = zi; bur = ur; bui = ui;
        float* Lb = &g_aggL[((size_t)fidx * KD + k) * 4];
        Lb[0] = bzr; Lb[1] = bzi; Lb[2] = bur; Lb[3] = bui;
    }
    __syncthreads();
    if (tid == 0) {
        __threadfence();
        atomicExch(&g_flag[fidx], 1);
    }

    // ---------- decoupled lookback ----------
    if (tid < 64) {
        float czr = 1.0f, czi = 0.0f, cur = 0.0f, cui = 0.0f;
        int p = chunk - 1;
        while (p >= 0) {
            int f;
            volatile int* vf = (volatile int*)&g_flag[b * NCHUNK2 + p];
            do { f = *vf; } while (f == 0);
            __threadfence();
            const float* src = (f == 2)
                ? &g_aggI[(((size_t)b * NCHUNK2 + p) * KD + k) * 4]
                : &g_aggL[(((size_t)b * NCHUNK2 + p) * KD + k) * 4];
            float azr = __ldcg(&src[0]);
            float azi = __ldcg(&src[1]);
            float aur = __ldcg(&src[2]);
            float aui = __ldcg(&src[3]);
            float nzr = czr * azr - czi * azi;
            float nzi = czr * azi + czi * azr;
            float nur = fmaf(czr, aur, fmaf(-czi, aui, cur));
            float nui = fmaf(czr, aui, fmaf(czi, aur, cui));
            czr = nzr; czi = nzi; cur = nur; cui = nui;
            if (f == 2) break;
            p--;
        }
        carry[k] = cur;
        carry[64 + k] = cui;
        float izr = bzr * czr - bzi * czi;
        float izi = bzr * czi + bzi * czr;
        float iur = fmaf(bzr, cur, fmaf(-bzi, cui, bur));
        float iui = fmaf(bzr, cui, fmaf(bzi, cur, bui));
        float* Ib = &g_aggI[((size_t)fidx * KD + k) * 4];
        Ib[0] = izr; Ib[1] = izi; Ib[2] = iur; Ib[3] = iui;
    }
    __syncthreads();
    if (tid == 0) {
        __threadfence();
        atomicExch(&g_flag[fidx], 2);
    }

    // ---------- replay with carry, write output ----------
    float pzr = pre[(g * 64 + k) * 4 + 0];
    float pzi = pre[(g * 64 + k) * 4 + 1];
    float pur = pre[(g * 64 + k) * 4 + 2];
    float pui = pre[(g * 64 + k) * 4 + 3];
    float chr_ = carry[k];
    float chi  = carry[64 + k];
    float hr = fmaf(pzr, chr_, fmaf(-pzi, chi, pur));
    float hi = fmaf(pzr, chi, fmaf(pzi, chr_, pui));

    float* outp = out + base_bt * (2 * KD);
#pragma unroll 4
    for (int i = 0; i < GLEN; i++) {
        float rc, rs;
        zval2(amp[(size_t)i * KD], omp_[(size_t)i * KD], tmp_[i], dtp[i], a0k, w0k, rc, rs);
        float u = fmaf(up_[(size_t)i * KD], invs, bk);
        float hr2 = fmaf(rc, hr, fmaf(-rs, hi, u));
        float hi2 = fmaf(rc, hi, rs * hr);
        hr = hr2; hi = hi2;
        outp[(size_t)i * 128 + k]      = hr;
        outp[(size_t)i * 128 + 64 + k] = hi;
    }
}

// ---------------- launch ----------------
extern "C" void kernel_launch(void* const* d_in, const int* in_sizes, int n_in,
                              void* d_out, int out_size) {
    const float* x      = (const float*)d_in[0];
    const float* dt     = (const float*)d_in[1];
    const float* amod   = (const float*)d_in[2];
    const float* omod   = (const float*)d_in[3];
    const float* tmod   = (const float*)d_in[4];
    const float* s_real = (const float*)d_in[5];
    const float* s_imag = (const float*)d_in[6];
    const float* tau_r  = (const float*)d_in[7];
    const float* W      = (const float*)d_in[8];
    const float* bvec   = (const float*)d_in[9];
    float* out = (float*)d_out;

    // smem = max(prep overlay, GEMM tiles)
    static const size_t prep_f = 128 * 68 + 3 * 64 * 68 + 3 * 64;   // 21952 floats
    static const size_t gemm_f = 256 * 36 + 32 * 64;                //  11264 floats
    static const size_t smem = (prep_f > gemm_f ? prep_f : gemm_f) * sizeof(float);

    cudaFuncSetAttribute(gemm_kernel, cudaFuncAttributeMaxDynamicSharedMemorySize, (int)smem);

    gemm_kernel<<<NGEMM + 1, NTHREADS, smem>>>(x, W, bvec, s_real, s_imag, tau_r);
    scan_kernel<<<NSCAN, NTHREADS>>>(dt, amod, omod, tmod, out);
}